// round 16
// baseline (speedup 1.0000x reference)
#include <cuda_runtime.h>
#include <math.h>

// DoMINO point-MLP, TWO (point,neighbor) items per thread (same point),
// weight LDS shared between items (3 CTAs/SM), f32x2 packed math,
// hardware MUFU.TANH activations. Features stored ITEM-PACKED (fa,fb)
// [66 regs, not 132] with broadcast pairs rebuilt at use -> no spill.
// 33 -> 64 (gelu) -> 32 (gelu) -> 8 (tanh), masked sum over P=10,
// out (8,64,48,32) fp32, reduced via global RED into pre-zeroed d_out.

namespace {
constexpr int N_PTS = 98304;       // 64*48*32
constexpr int NB    = 10;
constexpr int NITEM = N_PTS * NB;  // 983040
constexpr int NTHRD = NITEM / 2;   // 491520 threads, 2 items each
// shared layout (floats); all offsets even -> 8B/16B aligned views OK
constexpr int OFF_W1 = 0;      // 33*64 = 2112
constexpr int OFF_B1 = 2112;   // 64
constexpr int OFF_W2 = 2176;   // 64*32 = 2048
constexpr int OFF_B2 = 4224;   // 32
constexpr int OFF_W3 = 4256;   // 32*8 = 256
constexpr int OFF_B3 = 4512;   // 8
constexpr int OFF_FR = 4520;   // 5 (+3 pad)
constexpr int SM_TOT = 4528;
}

typedef unsigned long long u64;

__device__ __forceinline__ u64 pk2(float x, float y) {
    u64 r;
    asm("mov.b64 %0, {%1, %2};" : "=l"(r) : "f"(x), "f"(y));
    return r;
}
__device__ __forceinline__ void up2(u64 a, float& x, float& y) {
    asm("mov.b64 {%0, %1}, %2;" : "=f"(x), "=f"(y) : "l"(a));
}
// packed dual fp32 FMA (accumulate form): d = a*b + d
__device__ __forceinline__ void fma2(u64& d, u64 a, u64 b) {
    asm("fma.rn.f32x2 %0, %1, %2, %0;" : "+l"(d) : "l"(a), "l"(b));
}
// packed dual fp32 FMA (3-operand): r = a*b + c
__device__ __forceinline__ u64 vfma2(u64 a, u64 b, u64 c) {
    u64 r;
    asm("fma.rn.f32x2 %0, %1, %2, %3;" : "=l"(r) : "l"(a), "l"(b), "l"(c));
    return r;
}
__device__ __forceinline__ u64 vmul2(u64 a, u64 b) {
    u64 r;
    asm("mul.rn.f32x2 %0, %1, %2;" : "=l"(r) : "l"(a), "l"(b));
    return r;
}
__device__ __forceinline__ u64 vadd2(u64 a, u64 b) {
    u64 r;
    asm("add.rn.f32x2 %0, %1, %2;" : "=l"(r) : "l"(a), "l"(b));
    return r;
}
__device__ __forceinline__ u64 C2(float c) { return pk2(c, c); }
// hardware tanh (MUFU.TANH) on both halves of a packed pair
__device__ __forceinline__ u64 vtanh2(u64 a) {
    float x, y; up2(a, x, y);
    float rx, ry;
    asm("tanh.approx.f32 %0, %1;" : "=f"(rx) : "f"(x));
    asm("tanh.approx.f32 %0, %1;" : "=f"(ry) : "f"(y));
    return pk2(rx, ry);
}

// Vector GELU, tanh form with hardware MUFU.TANH:
// gelu(v) = 0.5*v*(1 + tanh(0.7978845608*(v + 0.044715*v^3)))
__device__ __forceinline__ u64 gelu2(u64 v) {
    u64 v2 = vmul2(v, v);
    u64 t  = vfma2(C2(0.0356774081f), v2, C2(0.7978845608f)); // 0.7979 + 0.035677*v^2
    u64 u  = vmul2(v, t);                                     // arg
    u64 th = vtanh2(u);
    u64 hv = vmul2(v, C2(0.5f));
    return vfma2(hv, th, hv);                                 // 0.5v + 0.5v*th
}

__global__ void zero_out_kernel(float* __restrict__ out, int n4) {
    int i = blockIdx.x * blockDim.x + threadIdx.x;
    if (i < n4) reinterpret_cast<float4*>(out)[i] = make_float4(0.f, 0.f, 0.f, 0.f);
}

__global__ void __launch_bounds__(128, 3)
domino_kernel(const float* __restrict__ x,
              const float* __restrict__ freqs,
              const float* __restrict__ W1, const float* __restrict__ b1,
              const float* __restrict__ W2, const float* __restrict__ b2,
              const float* __restrict__ W3, const float* __restrict__ b3,
              float* __restrict__ out)
{
    __shared__ __align__(16) float sm[SM_TOT];

    // stage weights/biases/freqs into shared (broadcast source for the block)
    for (int i = threadIdx.x; i < 2112; i += blockDim.x) sm[OFF_W1 + i] = W1[i];
    for (int i = threadIdx.x; i < 64;   i += blockDim.x) sm[OFF_B1 + i] = b1[i];
    for (int i = threadIdx.x; i < 2048; i += blockDim.x) sm[OFF_W2 + i] = W2[i];
    for (int i = threadIdx.x; i < 32;   i += blockDim.x) sm[OFF_B2 + i] = b2[i];
    for (int i = threadIdx.x; i < 256;  i += blockDim.x) sm[OFF_W3 + i] = W3[i];
    for (int i = threadIdx.x; i < 8;    i += blockDim.x) sm[OFF_B3 + i] = b3[i];
    for (int i = threadIdx.x; i < 8;    i += blockDim.x) sm[OFF_FR + i] = (i < 5) ? freqs[i] : 0.0f;
    __syncthreads();

    const int t = blockIdx.x * blockDim.x + threadIdx.x;   // grid exact
    const int n = t / 5;                                   // output point index

    // items 2t and 2t+1 (same point): 6 consecutive floats, 8B aligned
    const float2* xv = reinterpret_cast<const float2*>(x + (size_t)t * 6);
    const float2 v0 = xv[0], v1 = xv[1], v2 = xv[2];
    const float xa0 = v0.x, xa1 = v0.y, xa2 = v1.x;
    const float xb0 = v1.y, xb1 = v2.x, xb2 = v2.y;
    const float ma = (fabsf(xa0) > 1e-6f) ? 1.0f : 0.0f;   // padded-neighbor masks
    const float mb = (fabsf(xb0) > 1e-6f) ? 1.0f : 0.0f;

    // double2 = 4 floats. Row sizes in double2: W1 row(64f)=16, W2 row(32f)=8, W3 row(8f)=2.
    const double2* W1v = reinterpret_cast<const double2*>(sm + OFF_W1);
    const u64*     b1v = reinterpret_cast<const u64*>(sm + OFF_B1);
    const double2* W2v = reinterpret_cast<const double2*>(sm + OFF_W2);
    const u64*     b2v = reinterpret_cast<const u64*>(sm + OFF_B2);
    const double2* W3v = reinterpret_cast<const double2*>(sm + OFF_W3);
    const u64*     b3v = reinterpret_cast<const u64*>(sm + OFF_B3);

    // ---- feature vectors, ITEM-PACKED: fp[i] = (fa_i, fb_i), 33 u64 ----
    u64 fp[33];
    fp[0] = pk2(xa0, xb0); fp[1] = pk2(xa1, xb1); fp[2] = pk2(xa2, xb2);
    {
#pragma unroll
        for (int m = 0; m < 5; m++) {
            const u64 frm2 = C2(sm[OFF_FR + m]);
#pragma unroll
            for (int d = 0; d < 3; d++) {
                float ta_, tb_;
                up2(vmul2(fp[d], frm2), ta_, tb_);    // one packed mul for both args
                float sa, caa, sb, cbb;
                __sincosf(ta_, &sa, &caa);
                __sincosf(tb_, &sb, &cbb);
                fp[3  + m * 3 + d] = pk2(sa, sb);
                fp[18 + m * 3 + d] = pk2(caa, cbb);
            }
        }
    }

    // ---- layer 2 accumulators (32 outputs = 16 packed) per item ----
    u64 a2a[16], a2b[16];
#pragma unroll
    for (int kp = 0; kp < 16; kp++) { a2a[kp] = b2v[kp]; a2b[kp] = a2a[kp]; }

    // ---- layer 1 in 4 chunks of 16 outputs, streamed into layer 2 ----
#pragma unroll 1
    for (int jc = 0; jc < 4; jc++) {
        u64 c1a[8], c1b[8];
#pragma unroll
        for (int q = 0; q < 8; q++) { c1a[q] = b1v[jc * 8 + q]; c1b[q] = c1a[q]; }

#pragma unroll
        for (int i = 0; i < 33; i++) {
            float fva, fvb;
            up2(fp[i], fva, fvb);
            const u64 ffa = pk2(fva, fva);           // broadcast pairs rebuilt at use
            const u64 ffb = pk2(fvb, fvb);
            const double2* wrow = W1v + i * 16 + jc * 4;
#pragma unroll
            for (int q = 0; q < 4; q++) {
                const double2 w = wrow[q];           // one LDS.128, serves both items
                const u64 wx = __double_as_longlong(w.x);
                const u64 wy = __double_as_longlong(w.y);
                fma2(c1a[2 * q],     ffa, wx);
                fma2(c1a[2 * q + 1], ffa, wy);
                fma2(c1b[2 * q],     ffb, wx);
                fma2(c1b[2 * q + 1], ffb, wy);
            }
        }

        // gelu all 16 chunk pairs (independent MUFU.TANH chains)
#pragma unroll
        for (int q = 0; q < 8; q++) {
            c1a[q] = gelu2(c1a[q]);
            c1b[q] = gelu2(c1b[q]);
        }

        // stream the activated chunk into layer 2
#pragma unroll
        for (int q = 0; q < 8; q++) {
            float gau, gav, gbu, gbv;
            up2(c1a[q], gau, gav);
            up2(c1b[q], gbu, gbv);
            const u64 hau = pk2(gau, gau);
            const u64 hav = pk2(gav, gav);
            const u64 hbu = pk2(gbu, gbu);
            const u64 hbv = pk2(gbv, gbv);
            const int j0 = jc * 16 + 2 * q;
            const double2* w2a = W2v + (size_t)j0 * 8;   // row j0 (8 double2 = 32 floats)
            const double2* w2b = w2a + 8;                // row j0+1
#pragma unroll
            for (int kq = 0; kq < 8; kq++) {
                const double2 wa = w2a[kq];              // one LDS.128 serves both items
                const u64 wax = __double_as_longlong(wa.x);
                const u64 way = __double_as_longlong(wa.y);
                fma2(a2a[2 * kq],     hau, wax);
                fma2(a2a[2 * kq + 1], hau, way);
                fma2(a2b[2 * kq],     hbu, wax);
                fma2(a2b[2 * kq + 1], hbu, way);
                const double2 wb = w2b[kq];
                const u64 wbx = __double_as_longlong(wb.x);
                const u64 wby = __double_as_longlong(wb.y);
                fma2(a2a[2 * kq],     hav, wbx);
                fma2(a2a[2 * kq + 1], hav, wby);
                fma2(a2b[2 * kq],     hbv, wbx);
                fma2(a2b[2 * kq + 1], hbv, wby);
            }
        }
    }

    // ---- layer 3: gelu all 32 pairs in place, then stream MACs ----
#pragma unroll
    for (int q = 0; q < 16; q++) {
        a2a[q] = gelu2(a2a[q]);
        a2b[q] = gelu2(a2b[q]);
    }

    u64 a3a[4], a3b[4];
#pragma unroll
    for (int cp = 0; cp < 4; cp++) { a3a[cp] = b3v[cp]; a3b[cp] = a3a[cp]; }
#pragma unroll
    for (int q = 0; q < 16; q++) {
        float gau, gav, gbu, gbv;
        up2(a2a[q], gau, gav);
        up2(a2b[q], gbu, gbv);
        const u64 hau = pk2(gau, gau);
        const u64 hav = pk2(gav, gav);
        const u64 hbu = pk2(gbu, gbu);
        const u64 hbv = pk2(gbv, gbv);
        const int k0 = 2 * q;
        const double2* w3a = W3v + (size_t)k0 * 2;   // row k0 (2 double2 = 8 floats)
        const double2* w3b = w3a + 2;                // row k0+1
#pragma unroll
        for (int cq = 0; cq < 2; cq++) {
            const double2 wa = w3a[cq];
            const double2 wb = w3b[cq];
            const u64 wax = __double_as_longlong(wa.x);
            const u64 way = __double_as_longlong(wa.y);
            const u64 wbx = __double_as_longlong(wb.x);
            const u64 wby = __double_as_longlong(wb.y);
            fma2(a3a[2 * cq],     hau, wax);
            fma2(a3a[2 * cq + 1], hau, way);
            fma2(a3a[2 * cq],     hav, wbx);
            fma2(a3a[2 * cq + 1], hav, wby);
            fma2(a3b[2 * cq],     hbu, wax);
            fma2(a3b[2 * cq + 1], hbu, way);
            fma2(a3b[2 * cq],     hbv, wbx);
            fma2(a3b[2 * cq + 1], hbv, wby);
        }
    }

    // ---- hardware tanh, mask-combine the two items, reduce via global RED ----
    const u64 ma2 = pk2(ma, ma);
    const u64 mb2 = pk2(mb, mb);
#pragma unroll
    for (int cp = 0; cp < 4; cp++) {
        const u64 ta = vtanh2(a3a[cp]);
        const u64 tb = vtanh2(a3b[cp]);
        u64 r = vmul2(ma2, ta);
        r = vfma2(mb2, tb, r);
        float r0, r1;
        up2(r, r0, r1);
        atomicAdd(&out[(size_t)(2 * cp)     * N_PTS + n], r0);
        atomicAdd(&out[(size_t)(2 * cp + 1) * N_PTS + n], r1);
    }
}

extern "C" void kernel_launch(void* const* d_in, const int* in_sizes, int n_in,
                              void* d_out, int out_size)
{
    (void)in_sizes; (void)n_in; (void)out_size;
    const float* x     = (const float*)d_in[0];
    // d_in[1] = grid : unused by the reference math
    const float* freqs = (const float*)d_in[2];
    const float* W1    = (const float*)d_in[3];
    const float* b1    = (const float*)d_in[4];
    const float* W2    = (const float*)d_in[5];
    const float* b2    = (const float*)d_in[6];
    const float* W3    = (const float*)d_in[7];
    const float* b3    = (const float*)d_in[8];
    float* out = (float*)d_out;

    // zero the output (8 * N_PTS floats = 786432 -> 196608 float4)
    const int n4 = (8 * N_PTS) / 4;
    zero_out_kernel<<<(n4 + 255) / 256, 256>>>(out, n4);

    domino_kernel<<<NTHRD / 128, 128>>>(x, freqs, W1, b1, W2, b2, W3, b3, out);
}